// round 2
// baseline (speedup 1.0000x reference)
#include <cuda_runtime.h>
#include <cstdint>

#define N_NODES 50000
#define N_EDGES 800000
#define N_GRAPHS 128
#define IN_CH 31
#define HID 64
#define EPS_IN 1e-5f

// ---------------- scratch (static device globals; no allocation) ----------------
__device__ float g_bufA[N_NODES * HID];
__device__ float g_bufB[N_NODES * HID];
__device__ float g_aggr[N_NODES * HID];
__device__ int g_deg[N_NODES];
__device__ int g_rowptr[N_NODES + 1];
__device__ int g_fill[N_NODES];
__device__ int g_csr[N_EDGES];
__device__ unsigned g_hbits[N_GRAPHS * 3 * HID];
__device__ float g_Wl1T[(3 * HID) * (2 * HID)];  // [c][o] c<192, o<128
__device__ float g_Wl2T[(2 * HID) * (HID / 2)];  // [c][o] c<128, o<32

// ---------------- init: zero degree histogram + h (relu outputs >= 0 -> 0-bits ok) ---
__global__ void k_zero() {
    int i = blockIdx.x * 256 + threadIdx.x;
    if (i < N_NODES) g_deg[i] = 0;
    if (i < N_GRAPHS * 3 * HID) g_hbits[i] = 0u;
}

// ---------------- CSR build ----------------
__global__ void k_hist(const int* __restrict__ dst) {
    int e = blockIdx.x * 256 + threadIdx.x;
    if (e < N_EDGES) atomicAdd(&g_deg[dst[e]], 1);
}

__global__ void k_scan() {
    __shared__ int buf[1024];
    __shared__ int carry;
    int tid = threadIdx.x;
    if (tid == 0) { carry = 0; g_rowptr[0] = 0; }
    __syncthreads();
    for (int base = 0; base < N_NODES; base += 1024) {
        int i = base + tid;
        int v = (i < N_NODES) ? g_deg[i] : 0;
        buf[tid] = v;
        __syncthreads();
        for (int off = 1; off < 1024; off <<= 1) {
            int add = (tid >= off) ? buf[tid - off] : 0;
            __syncthreads();
            buf[tid] += add;
            __syncthreads();
        }
        int incl = buf[tid];
        if (i < N_NODES) {
            g_rowptr[i + 1] = carry + incl;
            g_fill[i] = carry + incl - v;  // exclusive
        }
        __syncthreads();
        if (tid == 1023) carry += buf[1023];
        __syncthreads();
    }
}

__global__ void k_scatter(const int* __restrict__ src, const int* __restrict__ dst) {
    int e = blockIdx.x * 256 + threadIdx.x;
    if (e < N_EDGES) {
        int p = atomicAdd(&g_fill[dst[e]], 1);
        g_csr[p] = src[e];
    }
}

// ---------------- transpose head weights for coalesced reads ----------------
__global__ void k_transpose(const float* __restrict__ Wl1, const float* __restrict__ Wl2) {
    int i = blockIdx.x * 256 + threadIdx.x;
    if (i < 128 * 192) {
        int o = i / 192, c = i % 192;
        g_Wl1T[c * 128 + o] = Wl1[i];
    }
    if (i < 32 * 128) {
        int o = i / 128, c = i % 128;
        g_Wl2T[c * 32 + o] = Wl2[i];
    }
}

// ---------------- one-pass segment softmax aggregation (warp per node) ----------------
// aggr[n,c] = sum_e m*exp(t*m) / sum_e exp(t*m)  over incoming edges of n
// (shift-invariance of softmax; logits bounded so exp cannot overflow)
template <int C>
__global__ __launch_bounds__(256) void k_aggr(const float* __restrict__ xin,
                                              const float* __restrict__ tptr,
                                              float* __restrict__ aggr) {
    int warp = (blockIdx.x * blockDim.x + threadIdx.x) >> 5;
    int lane = threadIdx.x & 31;
    if (warp >= N_NODES) return;
    float t = __ldg(tptr);
    int beg = g_rowptr[warp];
    int end = g_rowptr[warp + 1];
    float num0 = 0.f, den0 = 0.f, num1 = 0.f, den1 = 0.f;
    const int c0 = lane;
    const int c1 = lane + 32;
    for (int k = beg; k < end; k++) {
        int s = g_csr[k];
        const float* row = xin + (size_t)s * C;
        if (c0 < C) {
            float v = row[c0];
            float e = __expf(v * t);
            den0 += e;
            num0 += v * e;
        }
        if (C > 32) {
            float v = row[c1];
            float e = __expf(v * t);
            den1 += e;
            num1 += v * e;
        }
    }
    float* orow = aggr + (size_t)warp * C;
    if (c0 < C) orow[c0] = (den0 > 0.f) ? num0 / den0 : 0.f;
    if (C > 32 && c1 < C) orow[c1] = (den1 > 0.f) ? num1 / den1 : 0.f;
}

// ---------------- dual GEMM: y[n,o] = b[o] + aggr[n,:]@Wr[o,:] + x[n,:]@Ws[o,:] ----------
// 16 nodes per block, 16 threads per node, 4 outputs per thread.
template <int C>
__global__ __launch_bounds__(256) void k_lin(const float* __restrict__ xin,
                                             const float* __restrict__ aggr,
                                             const float* __restrict__ Wr,
                                             const float* __restrict__ br,
                                             const float* __restrict__ Ws,
                                             float* __restrict__ y) {
    __shared__ __align__(16) float sWr[C * HID];  // [c][o]
    __shared__ __align__(16) float sWs[C * HID];  // [c][o]
    __shared__ __align__(16) float sb[HID];
    __shared__ float sx[16 * C];
    __shared__ float sa[16 * C];
    int tid = threadIdx.x;
    for (int i = tid; i < C * HID; i += 256) {
        int o = i / C, c = i % C;
        sWr[c * HID + o] = Wr[i];
        sWs[c * HID + o] = Ws[i];
    }
    if (tid < HID) sb[tid] = br[tid];
    int base = blockIdx.x * 16 * C;
    for (int i = tid; i < 16 * C; i += 256) {
        sx[i] = xin[base + i];
        sa[i] = aggr[base + i];
    }
    __syncthreads();

    int nl = tid >> 4;
    int o0 = (tid & 15) * 4;
    const float* pa = &sa[nl * C];
    const float* px = &sx[nl * C];
    float4 acc = *(const float4*)&sb[o0];
#pragma unroll 4
    for (int c = 0; c < C; c++) {
        float a = pa[c];
        float xv = px[c];
        float4 wr = *(const float4*)&sWr[c * HID + o0];
        float4 ws = *(const float4*)&sWs[c * HID + o0];
        acc.x += a * wr.x + xv * ws.x;
        acc.y += a * wr.y + xv * ws.y;
        acc.z += a * wr.z + xv * ws.z;
        acc.w += a * wr.w + xv * ws.w;
    }
    int n = blockIdx.x * 16 + nl;
    *(float4*)&y[(size_t)n * HID + o0] = acc;
}

// ---------------- instance norm + relu (in place) + per-graph segmax into h ----------
__global__ __launch_bounds__(256) void k_norm(float* __restrict__ y,
                                              const int* __restrict__ batch,
                                              int loff) {
    int warp = (blockIdx.x * blockDim.x + threadIdx.x) >> 5;
    int lane = threadIdx.x & 31;
    if (warp >= N_NODES) return;
    float v0 = y[(size_t)warp * HID + lane];
    float v1 = y[(size_t)warp * HID + lane + 32];
    float s = v0 + v1;
#pragma unroll
    for (int o = 16; o; o >>= 1) s += __shfl_xor_sync(0xFFFFFFFFu, s, o);
    float mu = s * (1.0f / HID);
    float d0 = v0 - mu, d1 = v1 - mu;
    float q = d0 * d0 + d1 * d1;
#pragma unroll
    for (int o = 16; o; o >>= 1) q += __shfl_xor_sync(0xFFFFFFFFu, q, o);
    float r = rsqrtf(q * (1.0f / HID) + EPS_IN);
    float o0 = fmaxf(d0 * r, 0.f);
    float o1 = fmaxf(d1 * r, 0.f);
    y[(size_t)warp * HID + lane] = o0;
    y[(size_t)warp * HID + lane + 32] = o1;
    int g = batch[warp];
    unsigned* hrow = g_hbits + g * (3 * HID) + loff;
    // relu output >= 0 -> float bit pattern is monotone as unsigned
    atomicMax(&hrow[lane], __float_as_uint(o0));
    atomicMax(&hrow[lane + 32], __float_as_uint(o1));
}

// ---------------- head MLP: one block per graph ----------------
__global__ __launch_bounds__(192) void k_final(const float* __restrict__ bl1,
                                               const float* __restrict__ bl2,
                                               float* __restrict__ out) {
    __shared__ float sh[3 * HID];
    __shared__ float sz1[2 * HID];
    __shared__ float sz2[HID / 2];
    int g = blockIdx.x;
    int tid = threadIdx.x;
    sh[tid] = __uint_as_float(g_hbits[g * (3 * HID) + tid]);
    __syncthreads();
    if (tid < 2 * HID) {
        float acc = bl1[tid];
#pragma unroll 4
        for (int c = 0; c < 3 * HID; c++) acc += sh[c] * g_Wl1T[c * (2 * HID) + tid];
        sz1[tid] = fmaxf(acc, 0.f);
    }
    __syncthreads();
    if (tid < HID / 2) {
        float acc = bl2[tid];
#pragma unroll 4
        for (int c = 0; c < 2 * HID; c++) acc += sz1[c] * g_Wl2T[c * (HID / 2) + tid];
        sz2[tid] = acc;
    }
    __syncthreads();
    if (tid < 32) {
        float v = sz2[tid];
        float q = v * v;
#pragma unroll
        for (int o = 16; o; o >>= 1) q += __shfl_xor_sync(0xFFFFFFFFu, q, o);
        float nrm = fmaxf(sqrtf(q), 1e-12f);
        out[g * 32 + tid] = v / nrm;
    }
}

// ---------------- launch ----------------
extern "C" void kernel_launch(void* const* d_in, const int* in_sizes, int n_in,
                              void* d_out, int out_size) {
    const float* x = (const float*)d_in[0];
    const int* ei = (const int*)d_in[1];
    const int* src = ei;
    const int* dst = ei + N_EDGES;
    const int* batch = (const int*)d_in[2];
    const float* t = (const float*)d_in[3];
    const float* W1r = (const float*)d_in[4];
    const float* b1 = (const float*)d_in[5];
    const float* W1s = (const float*)d_in[6];
    const float* W2r = (const float*)d_in[7];
    const float* b2 = (const float*)d_in[8];
    const float* W2s = (const float*)d_in[9];
    const float* W3r = (const float*)d_in[10];
    const float* b3 = (const float*)d_in[11];
    const float* W3s = (const float*)d_in[12];
    const float* Wl1 = (const float*)d_in[13];
    const float* bl1 = (const float*)d_in[14];
    const float* Wl2 = (const float*)d_in[15];
    const float* bl2 = (const float*)d_in[16];
    float* out = (float*)d_out;

    float *bufA, *bufB, *aggr;
    cudaGetSymbolAddress((void**)&bufA, g_bufA);
    cudaGetSymbolAddress((void**)&bufB, g_bufB);
    cudaGetSymbolAddress((void**)&aggr, g_aggr);

    const int ZB = (N_NODES + 255) / 256;          // covers 50000 > 24576
    const int EB = (N_EDGES + 255) / 256;          // 3125
    const int WB = (N_NODES * 32 + 255) / 256;     // warp-per-node grids: 6250
    const int LB = N_NODES / 16;                   // 3125 (divides exactly)

    k_zero<<<ZB, 256>>>();
    k_hist<<<EB, 256>>>(dst);
    k_scan<<<1, 1024>>>();
    k_scatter<<<EB, 256>>>(src, dst);
    k_transpose<<<(128 * 192 + 255) / 256, 256>>>(Wl1, Wl2);

    // layer 1 (C_in = 31)
    k_aggr<IN_CH><<<WB, 256>>>(x, t, aggr);
    k_lin<IN_CH><<<LB, 256>>>(x, aggr, W1r, b1, W1s, bufA);
    k_norm<<<WB, 256>>>(bufA, batch, 0);

    // layer 2
    k_aggr<HID><<<WB, 256>>>(bufA, t, aggr);
    k_lin<HID><<<LB, 256>>>(bufA, aggr, W2r, b2, W2s, bufB);
    k_norm<<<WB, 256>>>(bufB, batch, HID);

    // layer 3
    k_aggr<HID><<<WB, 256>>>(bufB, t, aggr);
    k_lin<HID><<<LB, 256>>>(bufB, aggr, W3r, b3, W3s, bufA);
    k_norm<<<WB, 256>>>(bufA, batch, 2 * HID);

    k_final<<<N_GRAPHS, 192>>>(bl1, bl2, out);
    (void)in_sizes; (void)n_in; (void)out_size;
}

// round 3
// speedup vs baseline: 1.3161x; 1.3161x over previous
#include <cuda_runtime.h>
#include <cstdint>

#define N_NODES 50000
#define N_EDGES 800000
#define N_GRAPHS 128
#define IN_CH 31
#define HID 64
#define EPS_IN 1e-5f

#define SCAN_B 1024
#define SCAN_NB ((N_NODES + SCAN_B - 1) / SCAN_B)  // 49

// ---------------- scratch (static device globals; no allocation) ----------------
__device__ float g_bufA[N_NODES * HID];
__device__ float g_bufB[N_NODES * HID];
__device__ float g_aggr[N_NODES * HID];
__device__ int g_deg[N_NODES];
__device__ int g_rowptr[N_NODES + 1];
__device__ int g_fill[N_NODES];
__device__ int g_csr[N_EDGES];
__device__ int g_part[SCAN_NB];
__device__ int g_partoff[SCAN_NB];
__device__ unsigned g_hbits[N_GRAPHS * 3 * HID];
__device__ float g_Wl1T[(3 * HID) * (2 * HID)];  // [c][o] c<192, o<128
__device__ float g_Wl2T[(2 * HID) * (HID / 2)];  // [c][o] c<128, o<32

// ---------------- init ----------------
__global__ void k_zero() {
    int i = blockIdx.x * 256 + threadIdx.x;
    if (i < N_NODES) g_deg[i] = 0;
    if (i < N_GRAPHS * 3 * HID) g_hbits[i] = 0u;
}

// ---------------- CSR build ----------------
__global__ void k_hist(const int* __restrict__ dst) {
    int e = blockIdx.x * 256 + threadIdx.x;
    if (e < N_EDGES) atomicAdd(&g_deg[dst[e]], 1);
}

// 3-phase multi-block exclusive scan of g_deg -> g_rowptr / g_fill
__global__ void k_scanA() {
    __shared__ int s[SCAN_B];
    int i = blockIdx.x * SCAN_B + threadIdx.x;
    s[threadIdx.x] = (i < N_NODES) ? g_deg[i] : 0;
    __syncthreads();
    for (int off = SCAN_B / 2; off; off >>= 1) {
        if (threadIdx.x < off) s[threadIdx.x] += s[threadIdx.x + off];
        __syncthreads();
    }
    if (threadIdx.x == 0) g_part[blockIdx.x] = s[0];
}

__global__ void k_scanB() {
    __shared__ int s[64];
    int tid = threadIdx.x;
    int v = (tid < SCAN_NB) ? g_part[tid] : 0;
    s[tid] = v;
    __syncthreads();
    for (int off = 1; off < 64; off <<= 1) {
        int a = (tid >= off) ? s[tid - off] : 0;
        __syncthreads();
        s[tid] += a;
        __syncthreads();
    }
    if (tid < SCAN_NB) g_partoff[tid] = s[tid] - v;  // exclusive
    if (tid == 0) g_rowptr[0] = 0;
}

__global__ void k_scanC() {
    __shared__ int s[SCAN_B];
    int i = blockIdx.x * SCAN_B + threadIdx.x;
    int v = (i < N_NODES) ? g_deg[i] : 0;
    s[threadIdx.x] = v;
    __syncthreads();
    for (int off = 1; off < SCAN_B; off <<= 1) {
        int a = (threadIdx.x >= off) ? s[threadIdx.x - off] : 0;
        __syncthreads();
        s[threadIdx.x] += a;
        __syncthreads();
    }
    if (i < N_NODES) {
        int incl = s[threadIdx.x] + g_partoff[blockIdx.x];
        g_rowptr[i + 1] = incl;
        g_fill[i] = incl - v;  // exclusive
    }
}

__global__ void k_scatter(const int* __restrict__ src, const int* __restrict__ dst) {
    int e = blockIdx.x * 256 + threadIdx.x;
    if (e < N_EDGES) {
        int p = atomicAdd(&g_fill[dst[e]], 1);
        g_csr[p] = src[e];
    }
}

// ---------------- transpose head weights for coalesced reads ----------------
__global__ void k_transpose(const float* __restrict__ Wl1, const float* __restrict__ Wl2) {
    int i = blockIdx.x * 256 + threadIdx.x;
    if (i < 128 * 192) {
        int o = i / 192, c = i % 192;
        g_Wl1T[c * 128 + o] = Wl1[i];
    }
    if (i < 32 * 128) {
        int o = i / 128, c = i % 128;
        g_Wl2T[c * 32 + o] = Wl2[i];
    }
}

// ---------------- one-pass segment softmax aggregation ----------------
// aggr[n,c] = sum_e v*exp(t*v) / sum_e exp(t*v)  (shift-invariant; logits bounded)
// C=64: warp per node, float2 per lane, edge loop unrolled x4 for MLP.
__global__ __launch_bounds__(256) void k_aggr64(const float* __restrict__ xin,
                                                const float* __restrict__ tptr,
                                                float* __restrict__ aggr) {
    int node = (blockIdx.x * 256 + threadIdx.x) >> 5;
    int lane = threadIdx.x & 31;
    if (node >= N_NODES) return;
    float t = __ldg(tptr);
    int beg = g_rowptr[node];
    int end = g_rowptr[node + 1];
    float nx = 0.f, ny = 0.f, dx = 0.f, dy = 0.f;
    int co = 2 * lane;
    int k = beg;
#define ACC2(v)                        \
    {                                  \
        float e0 = __expf((v).x * t);  \
        float e1 = __expf((v).y * t);  \
        dx += e0; nx += (v).x * e0;    \
        dy += e1; ny += (v).y * e1;    \
    }
    for (; k + 4 <= end; k += 4) {
        int s0 = g_csr[k], s1 = g_csr[k + 1], s2 = g_csr[k + 2], s3 = g_csr[k + 3];
        float2 v0 = *(const float2*)(xin + (size_t)s0 * HID + co);
        float2 v1 = *(const float2*)(xin + (size_t)s1 * HID + co);
        float2 v2 = *(const float2*)(xin + (size_t)s2 * HID + co);
        float2 v3 = *(const float2*)(xin + (size_t)s3 * HID + co);
        ACC2(v0) ACC2(v1) ACC2(v2) ACC2(v3)
    }
    for (; k < end; k++) {
        int s = g_csr[k];
        float2 v = *(const float2*)(xin + (size_t)s * HID + co);
        ACC2(v)
    }
#undef ACC2
    float2 o;
    o.x = (dx > 0.f) ? nx / dx : 0.f;
    o.y = (dy > 0.f) ? ny / dy : 0.f;
    *(float2*)(aggr + (size_t)node * HID + co) = o;
}

// C=31: warp per node, scalar per lane (lane<31), edge loop unrolled x4.
__global__ __launch_bounds__(256) void k_aggr31(const float* __restrict__ xin,
                                                const float* __restrict__ tptr,
                                                float* __restrict__ aggr) {
    int node = (blockIdx.x * 256 + threadIdx.x) >> 5;
    int lane = threadIdx.x & 31;
    if (node >= N_NODES) return;
    float t = __ldg(tptr);
    int beg = g_rowptr[node];
    int end = g_rowptr[node + 1];
    int cc = (lane < IN_CH) ? lane : 0;  // lane 31 reads a safe dummy
    float num = 0.f, den = 0.f;
    int k = beg;
#define ACC1(v)                       \
    {                                 \
        float e = __expf((v) * t);    \
        den += e; num += (v) * e;     \
    }
    for (; k + 4 <= end; k += 4) {
        int s0 = g_csr[k], s1 = g_csr[k + 1], s2 = g_csr[k + 2], s3 = g_csr[k + 3];
        float v0 = xin[(size_t)s0 * IN_CH + cc];
        float v1 = xin[(size_t)s1 * IN_CH + cc];
        float v2 = xin[(size_t)s2 * IN_CH + cc];
        float v3 = xin[(size_t)s3 * IN_CH + cc];
        ACC1(v0) ACC1(v1) ACC1(v2) ACC1(v3)
    }
    for (; k < end; k++) {
        float v = xin[(size_t)g_csr[k] * IN_CH + cc];
        ACC1(v)
    }
#undef ACC1
    if (lane < IN_CH)
        aggr[(size_t)node * IN_CH + lane] = (den > 0.f) ? num / den : 0.f;
}

// ---------------- fused dual-GEMM + instance-norm + relu + per-graph segmax -----------
// y[n,o] = b[o] + aggr[n,:]@Wr[o,:] + x[n,:]@Ws[o,:], then row-normalize, relu,
// write y and atomicMax into g_hbits. 32 nodes/block, 16 threads/node, 4 out/thread.
template <int C>
__global__ __launch_bounds__(512) void k_lin(const float* __restrict__ xin,
                                             const float* __restrict__ aggr,
                                             const float* __restrict__ Wr,
                                             const float* __restrict__ br,
                                             const float* __restrict__ Ws,
                                             const int* __restrict__ batch,
                                             int loff,
                                             float* __restrict__ y) {
    __shared__ __align__(16) float sWr[C * HID];  // [c][o]
    __shared__ __align__(16) float sWs[C * HID];  // [c][o]
    __shared__ __align__(16) float sb[HID];
    __shared__ float sx[32 * C];
    __shared__ float sa[32 * C];
    int tid = threadIdx.x;
    for (int i = tid; i < C * HID; i += 512) {
        int o = i / C, c = i % C;
        sWr[c * HID + o] = Wr[i];
        sWs[c * HID + o] = Ws[i];
    }
    if (tid < HID) sb[tid] = br[tid];
    long base = (long)blockIdx.x * 32 * C;
    long lim = (long)N_NODES * C;
    for (int i = tid; i < 32 * C; i += 512) {
        long gi = base + i;
        float xv = 0.f, av = 0.f;
        if (gi < lim) { xv = xin[gi]; av = aggr[gi]; }
        sx[i] = xv;
        sa[i] = av;
    }
    __syncthreads();

    int nl = tid >> 4;             // 0..31 node-in-block
    int o0 = (tid & 15) * 4;       // output quad
    const float* pa = &sa[nl * C];
    const float* px = &sx[nl * C];
    float4 acc = *(const float4*)&sb[o0];
#pragma unroll 4
    for (int c = 0; c < C; c++) {
        float a = pa[c];
        float xv = px[c];
        float4 wr = *(const float4*)&sWr[c * HID + o0];
        float4 ws = *(const float4*)&sWs[c * HID + o0];
        acc.x += a * wr.x + xv * ws.x;
        acc.y += a * wr.y + xv * ws.y;
        acc.z += a * wr.z + xv * ws.z;
        acc.w += a * wr.w + xv * ws.w;
    }

    // instance norm over the 64 outputs held by this 16-lane group
    float sum = acc.x + acc.y + acc.z + acc.w;
#pragma unroll
    for (int off = 8; off; off >>= 1) sum += __shfl_xor_sync(0xFFFFFFFFu, sum, off);
    float mu = sum * (1.0f / HID);
    float4 d;
    d.x = acc.x - mu; d.y = acc.y - mu; d.z = acc.z - mu; d.w = acc.w - mu;
    float q = d.x * d.x + d.y * d.y + d.z * d.z + d.w * d.w;
#pragma unroll
    for (int off = 8; off; off >>= 1) q += __shfl_xor_sync(0xFFFFFFFFu, q, off);
    float r = rsqrtf(q * (1.0f / HID) + EPS_IN);
    float4 o;
    o.x = fmaxf(d.x * r, 0.f);
    o.y = fmaxf(d.y * r, 0.f);
    o.z = fmaxf(d.z * r, 0.f);
    o.w = fmaxf(d.w * r, 0.f);

    int n = blockIdx.x * 32 + nl;
    if (n < N_NODES) {
        *(float4*)&y[(size_t)n * HID + o0] = o;
        int g = batch[n];
        unsigned* hrow = g_hbits + g * (3 * HID) + loff + o0;
        // relu output >= 0 -> float bits monotone as unsigned
        atomicMax(&hrow[0], __float_as_uint(o.x));
        atomicMax(&hrow[1], __float_as_uint(o.y));
        atomicMax(&hrow[2], __float_as_uint(o.z));
        atomicMax(&hrow[3], __float_as_uint(o.w));
    }
}

// ---------------- head MLP: one block per graph ----------------
__global__ __launch_bounds__(192) void k_final(const float* __restrict__ bl1,
                                               const float* __restrict__ bl2,
                                               float* __restrict__ out) {
    __shared__ float sh[3 * HID];
    __shared__ float sz1[2 * HID];
    __shared__ float sz2[HID / 2];
    int g = blockIdx.x;
    int tid = threadIdx.x;
    sh[tid] = __uint_as_float(g_hbits[g * (3 * HID) + tid]);
    __syncthreads();
    if (tid < 2 * HID) {
        float acc = bl1[tid];
#pragma unroll 4
        for (int c = 0; c < 3 * HID; c++) acc += sh[c] * g_Wl1T[c * (2 * HID) + tid];
        sz1[tid] = fmaxf(acc, 0.f);
    }
    __syncthreads();
    if (tid < HID / 2) {
        float acc = bl2[tid];
#pragma unroll 4
        for (int c = 0; c < 2 * HID; c++) acc += sz1[c] * g_Wl2T[c * (HID / 2) + tid];
        sz2[tid] = acc;
    }
    __syncthreads();
    if (tid < 32) {
        float v = sz2[tid];
        float q = v * v;
#pragma unroll
        for (int o = 16; o; o >>= 1) q += __shfl_xor_sync(0xFFFFFFFFu, q, o);
        float nrm = fmaxf(sqrtf(q), 1e-12f);
        out[g * 32 + tid] = v / nrm;
    }
}

// ---------------- launch ----------------
extern "C" void kernel_launch(void* const* d_in, const int* in_sizes, int n_in,
                              void* d_out, int out_size) {
    const float* x = (const float*)d_in[0];
    const int* ei = (const int*)d_in[1];
    const int* src = ei;
    const int* dst = ei + N_EDGES;
    const int* batch = (const int*)d_in[2];
    const float* t = (const float*)d_in[3];
    const float* W1r = (const float*)d_in[4];
    const float* b1 = (const float*)d_in[5];
    const float* W1s = (const float*)d_in[6];
    const float* W2r = (const float*)d_in[7];
    const float* b2 = (const float*)d_in[8];
    const float* W2s = (const float*)d_in[9];
    const float* W3r = (const float*)d_in[10];
    const float* b3 = (const float*)d_in[11];
    const float* W3s = (const float*)d_in[12];
    const float* Wl1 = (const float*)d_in[13];
    const float* bl1 = (const float*)d_in[14];
    const float* Wl2 = (const float*)d_in[15];
    const float* bl2 = (const float*)d_in[16];
    float* out = (float*)d_out;

    float *bufA, *bufB, *aggr;
    cudaGetSymbolAddress((void**)&bufA, g_bufA);
    cudaGetSymbolAddress((void**)&bufB, g_bufB);
    cudaGetSymbolAddress((void**)&aggr, g_aggr);

    const int ZB = (N_NODES + 255) / 256;
    const int EB = (N_EDGES + 255) / 256;
    const int WB = (N_NODES * 32 + 255) / 256;       // warp-per-node
    const int LB = (N_NODES + 31) / 32;              // 1563

    k_zero<<<ZB, 256>>>();
    k_hist<<<EB, 256>>>(dst);
    k_scanA<<<SCAN_NB, SCAN_B>>>();
    k_scanB<<<1, 64>>>();
    k_scanC<<<SCAN_NB, SCAN_B>>>();
    k_scatter<<<EB, 256>>>(src, dst);
    k_transpose<<<(128 * 192 + 255) / 256, 256>>>(Wl1, Wl2);

    // layer 1 (C_in = 31)
    k_aggr31<<<WB, 256>>>(x, t, aggr);
    k_lin<IN_CH><<<LB, 512>>>(x, aggr, W1r, b1, W1s, batch, 0, bufA);

    // layer 2
    k_aggr64<<<WB, 256>>>(bufA, t, aggr);
    k_lin<HID><<<LB, 512>>>(bufA, aggr, W2r, b2, W2s, batch, HID, bufB);

    // layer 3
    k_aggr64<<<WB, 256>>>(bufB, t, aggr);
    k_lin<HID><<<LB, 512>>>(bufB, aggr, W3r, b3, W3s, batch, 2 * HID, bufA);

    k_final<<<N_GRAPHS, 192>>>(bl1, bl2, out);
    (void)in_sizes; (void)n_in; (void)out_size;
}

// round 6
// speedup vs baseline: 1.9037x; 1.4465x over previous
#include <cuda_runtime.h>
#include <cstdint>

#define N_NODES 50000
#define N_EDGES 800000
#define N_GRAPHS 128
#define IN_CH 31
#define C_PAD 32
#define HID 64
#define EPS_IN 1e-5f

#define SCAN_B 1024
#define SCAN_NB ((N_NODES + SCAN_B - 1) / SCAN_B)  // 49

typedef unsigned long long u64;

// ---------------- scratch (static device globals; no allocation) ----------------
__device__ float g_xpad[N_NODES * C_PAD];
__device__ float g_bufA[N_NODES * HID];
__device__ float g_bufB[N_NODES * HID];
__device__ float g_aggr[N_NODES * HID];
__device__ int g_deg[N_NODES];
__device__ int g_rowptr[N_NODES + 1];
__device__ int g_fill[N_NODES];
__device__ int g_csr[N_EDGES];
__device__ int g_part[SCAN_NB];
__device__ int g_partoff[SCAN_NB];
__device__ unsigned g_hbits[N_GRAPHS * 3 * HID];
__device__ float g_Wl1T[(3 * HID) * (2 * HID)];
__device__ float g_Wl2T[(2 * HID) * (HID / 2)];

// ---------------- f32x2 packed helpers ----------------
__device__ __forceinline__ u64 pk2(float v) {
    u64 r;
    asm("mov.b64 %0, {%1, %1};" : "=l"(r) : "f"(v));
    return r;
}
__device__ __forceinline__ u64 ffma2(u64 a, u64 b, u64 c) {
    u64 d;
    asm("fma.rn.f32x2 %0, %1, %2, %3;" : "=l"(d) : "l"(a), "l"(b), "l"(c));
    return d;
}
__device__ __forceinline__ float2 up2(u64 v) {
    float2 f;
    asm("mov.b64 {%0, %1}, %2;" : "=f"(f.x), "=f"(f.y) : "l"(v));
    return f;
}

// ---------------- prep: zero deg/hbits, transpose head weights, pad x ----------------
__global__ void k_prep(const float* __restrict__ x,
                       const float* __restrict__ Wl1,
                       const float* __restrict__ Wl2) {
    int i = blockIdx.x * 256 + threadIdx.x;
    if (i < N_NODES * C_PAD) {
        int n = i >> 5, c = i & 31;
        g_xpad[i] = (c < IN_CH) ? x[n * IN_CH + c] : 0.f;
    }
    if (i < N_NODES) g_deg[i] = 0;
    if (i < N_GRAPHS * 3 * HID) g_hbits[i] = 0u;
    if (i < 128 * 192) {
        int o = i / 192, c = i % 192;
        g_Wl1T[c * 128 + o] = Wl1[i];
    }
    if (i < 32 * 128) {
        int o = i / 128, c = i % 128;
        g_Wl2T[c * 32 + o] = Wl2[i];
    }
}

// ---------------- CSR build ----------------
__global__ void k_hist(const int* __restrict__ dst) {
    int e = blockIdx.x * 256 + threadIdx.x;
    if (e < N_EDGES) atomicAdd(&g_deg[dst[e]], 1);
}

__global__ void k_scanA() {
    __shared__ int s[SCAN_B];
    int i = blockIdx.x * SCAN_B + threadIdx.x;
    s[threadIdx.x] = (i < N_NODES) ? g_deg[i] : 0;
    __syncthreads();
    for (int off = SCAN_B / 2; off; off >>= 1) {
        if (threadIdx.x < off) s[threadIdx.x] += s[threadIdx.x + off];
        __syncthreads();
    }
    if (threadIdx.x == 0) g_part[blockIdx.x] = s[0];
}

__global__ void k_scanB() {
    __shared__ int s[64];
    int tid = threadIdx.x;
    int v = (tid < SCAN_NB) ? g_part[tid] : 0;
    s[tid] = v;
    __syncthreads();
    for (int off = 1; off < 64; off <<= 1) {
        int a = (tid >= off) ? s[tid - off] : 0;
        __syncthreads();
        s[tid] += a;
        __syncthreads();
    }
    if (tid < SCAN_NB) g_partoff[tid] = s[tid] - v;
    if (tid == 0) g_rowptr[0] = 0;
}

__global__ void k_scanC() {
    __shared__ int s[SCAN_B];
    int i = blockIdx.x * SCAN_B + threadIdx.x;
    int v = (i < N_NODES) ? g_deg[i] : 0;
    s[threadIdx.x] = v;
    __syncthreads();
    for (int off = 1; off < SCAN_B; off <<= 1) {
        int a = (threadIdx.x >= off) ? s[threadIdx.x - off] : 0;
        __syncthreads();
        s[threadIdx.x] += a;
        __syncthreads();
    }
    if (i < N_NODES) {
        int incl = s[threadIdx.x] + g_partoff[blockIdx.x];
        g_rowptr[i + 1] = incl;
        g_fill[i] = incl - v;
    }
}

__global__ void k_scatter(const int* __restrict__ src, const int* __restrict__ dst) {
    int e = blockIdx.x * 256 + threadIdx.x;
    if (e < N_EDGES) {
        int p = atomicAdd(&g_fill[dst[e]], 1);
        g_csr[p] = src[e];
    }
}

// ---------------- one-pass segment softmax aggregation ----------------
// aggr[n,c] = sum_e v*exp(t*v) / sum_e exp(t*v)  (shift-invariant; logits bounded)
// C=32: warp per node, 1 float per lane (padded channel -> exact 0)
__global__ __launch_bounds__(256) void k_aggr32(const float* __restrict__ xin,
                                                const float* __restrict__ tptr,
                                                float* __restrict__ aggr) {
    int node = (blockIdx.x * 256 + threadIdx.x) >> 5;
    int lane = threadIdx.x & 31;
    if (node >= N_NODES) return;
    float t = __ldg(tptr);
    int beg = g_rowptr[node];
    int end = g_rowptr[node + 1];
    float num = 0.f, den = 0.f;
    int k = beg;
#define ACC1(v)                    \
    {                              \
        float e = __expf((v) * t); \
        den += e;                  \
        num += (v) * e;            \
    }
    for (; k + 4 <= end; k += 4) {
        int s0 = g_csr[k], s1 = g_csr[k + 1], s2 = g_csr[k + 2], s3 = g_csr[k + 3];
        float v0 = xin[(size_t)s0 * C_PAD + lane];
        float v1 = xin[(size_t)s1 * C_PAD + lane];
        float v2 = xin[(size_t)s2 * C_PAD + lane];
        float v3 = xin[(size_t)s3 * C_PAD + lane];
        ACC1(v0) ACC1(v1) ACC1(v2) ACC1(v3)
    }
    for (; k < end; k++) {
        float v = xin[(size_t)g_csr[k] * C_PAD + lane];
        ACC1(v)
    }
#undef ACC1
    aggr[(size_t)node * C_PAD + lane] = (den > 0.f) ? num / den : 0.f;
}

// C=64: warp per node, float2 per lane, edge loop unrolled x4 for MLP.
__global__ __launch_bounds__(256) void k_aggr64(const float* __restrict__ xin,
                                                const float* __restrict__ tptr,
                                                float* __restrict__ aggr) {
    int node = (blockIdx.x * 256 + threadIdx.x) >> 5;
    int lane = threadIdx.x & 31;
    if (node >= N_NODES) return;
    float t = __ldg(tptr);
    int beg = g_rowptr[node];
    int end = g_rowptr[node + 1];
    float nx = 0.f, ny = 0.f, dx = 0.f, dy = 0.f;
    int co = 2 * lane;
    int k = beg;
#define ACC2(v)                       \
    {                                 \
        float e0 = __expf((v).x * t); \
        float e1 = __expf((v).y * t); \
        dx += e0;                     \
        nx += (v).x * e0;             \
        dy += e1;                     \
        ny += (v).y * e1;             \
    }
    for (; k + 4 <= end; k += 4) {
        int s0 = g_csr[k], s1 = g_csr[k + 1], s2 = g_csr[k + 2], s3 = g_csr[k + 3];
        float2 v0 = *(const float2*)(xin + (size_t)s0 * HID + co);
        float2 v1 = *(const float2*)(xin + (size_t)s1 * HID + co);
        float2 v2 = *(const float2*)(xin + (size_t)s2 * HID + co);
        float2 v3 = *(const float2*)(xin + (size_t)s3 * HID + co);
        ACC2(v0) ACC2(v1) ACC2(v2) ACC2(v3)
    }
    for (; k < end; k++) {
        int s = g_csr[k];
        float2 v = *(const float2*)(xin + (size_t)s * HID + co);
        ACC2(v)
    }
#undef ACC2
    float2 o;
    o.x = (dx > 0.f) ? nx / dx : 0.f;
    o.y = (dy > 0.f) ? ny / dy : 0.f;
    *(float2*)(aggr + (size_t)node * HID + co) = o;
}

// ---------------- fused dual-GEMM + instance-norm + relu + per-graph segmax -----------
// y[n,o] = b[o] + aggr[n,:]@Wr[o,:] + x[n,:]@Ws[o,:]
// 256 threads: 16 o-quads x 16 node-groups of 8 nodes => 128 nodes/block.
// Weights staged in smem as [c][o] (f32x2 pairs); inputs read from global
// (broadcast across o-quad lanes, L1-resident). Packed fma.rn.f32x2 math.
template <int C, int CREAL>
__global__ __launch_bounds__(256) void k_lin(const float* __restrict__ xin,
                                             const float* __restrict__ aggr,
                                             const float* __restrict__ Wr,
                                             const float* __restrict__ br,
                                             const float* __restrict__ Ws,
                                             const int* __restrict__ batch,
                                             int loff,
                                             float* __restrict__ y) {
    __shared__ __align__(16) float sWr[C * HID];  // [c][o]
    __shared__ __align__(16) float sWs[C * HID];  // [c][o]
    __shared__ __align__(16) float sb[HID];
    int tid = threadIdx.x;
    for (int i = tid; i < C * HID; i += 256) {
        int o = i / C, c = i % C;
        float wr = (c < CREAL) ? Wr[o * CREAL + c] : 0.f;
        float ws = (c < CREAL) ? Ws[o * CREAL + c] : 0.f;
        sWr[c * HID + o] = wr;
        sWs[c * HID + o] = ws;
    }
    if (tid < HID) sb[tid] = br[tid];
    __syncthreads();

    int oq = tid & 15;
    int ng = tid >> 4;
    int o0 = oq * 4;
    int n0 = blockIdx.x * 128 + ng * 8;

    size_t rowoff[8];
#pragma unroll
    for (int n = 0; n < 8; n++) {
        int node = n0 + n;
        if (node >= N_NODES) node = N_NODES - 1;
        rowoff[n] = (size_t)node * C;
    }

    ulonglong2 b2 = *(const ulonglong2*)&sb[o0];
    u64 accA[8], accB[8];
#pragma unroll
    for (int n = 0; n < 8; n++) { accA[n] = b2.x; accB[n] = b2.y; }

    for (int c = 0; c < C; c += 4) {
        ulonglong2 wr0 = *(const ulonglong2*)&sWr[(c + 0) * HID + o0];
        ulonglong2 wr1 = *(const ulonglong2*)&sWr[(c + 1) * HID + o0];
        ulonglong2 wr2 = *(const ulonglong2*)&sWr[(c + 2) * HID + o0];
        ulonglong2 wr3 = *(const ulonglong2*)&sWr[(c + 3) * HID + o0];
        ulonglong2 ws0 = *(const ulonglong2*)&sWs[(c + 0) * HID + o0];
        ulonglong2 ws1 = *(const ulonglong2*)&sWs[(c + 1) * HID + o0];
        ulonglong2 ws2 = *(const ulonglong2*)&sWs[(c + 2) * HID + o0];
        ulonglong2 ws3 = *(const ulonglong2*)&sWs[(c + 3) * HID + o0];
#pragma unroll
        for (int n = 0; n < 8; n++) {
            float4 av = *(const float4*)(aggr + rowoff[n] + c);
            float4 xv = *(const float4*)(xin + rowoff[n] + c);
            u64 p;
            p = pk2(av.x); accA[n] = ffma2(p, wr0.x, accA[n]); accB[n] = ffma2(p, wr0.y, accB[n]);
            p = pk2(xv.x); accA[n] = ffma2(p, ws0.x, accA[n]); accB[n] = ffma2(p, ws0.y, accB[n]);
            p = pk2(av.y); accA[n] = ffma2(p, wr1.x, accA[n]); accB[n] = ffma2(p, wr1.y, accB[n]);
            p = pk2(xv.y); accA[n] = ffma2(p, ws1.x, accA[n]); accB[n] = ffma2(p, ws1.y, accB[n]);
            p = pk2(av.z); accA[n] = ffma2(p, wr2.x, accA[n]); accB[n] = ffma2(p, wr2.y, accB[n]);
            p = pk2(xv.z); accA[n] = ffma2(p, ws2.x, accA[n]); accB[n] = ffma2(p, ws2.y, accB[n]);
            p = pk2(av.w); accA[n] = ffma2(p, wr3.x, accA[n]); accB[n] = ffma2(p, wr3.y, accB[n]);
            p = pk2(xv.w); accA[n] = ffma2(p, ws3.x, accA[n]); accB[n] = ffma2(p, ws3.y, accB[n]);
        }
    }

    // epilogue: instance norm over 64 outputs (16-lane group) + relu + store + segmax
#pragma unroll
    for (int n = 0; n < 8; n++) {
        float2 p0 = up2(accA[n]);
        float2 p1 = up2(accB[n]);
        float sum = p0.x + p0.y + p1.x + p1.y;
#pragma unroll
        for (int off = 8; off; off >>= 1) sum += __shfl_xor_sync(0xFFFFFFFFu, sum, off);
        float mu = sum * (1.0f / HID);
        float d0 = p0.x - mu, d1 = p0.y - mu, d2 = p1.x - mu, d3 = p1.y - mu;
        float q = d0 * d0 + d1 * d1 + d2 * d2 + d3 * d3;
#pragma unroll
        for (int off = 8; off; off >>= 1) q += __shfl_xor_sync(0xFFFFFFFFu, q, off);
        float r = rsqrtf(q * (1.0f / HID) + EPS_IN);
        float4 o;
        o.x = fmaxf(d0 * r, 0.f);
        o.y = fmaxf(d1 * r, 0.f);
        o.z = fmaxf(d2 * r, 0.f);
        o.w = fmaxf(d3 * r, 0.f);
        int node = n0 + n;
        if (node < N_NODES) {
            *(float4*)&y[(size_t)node * HID + o0] = o;
            int g = batch[node];
            unsigned* hrow = g_hbits + g * (3 * HID) + loff + o0;
            atomicMax(&hrow[0], __float_as_uint(o.x));
            atomicMax(&hrow[1], __float_as_uint(o.y));
            atomicMax(&hrow[2], __float_as_uint(o.z));
            atomicMax(&hrow[3], __float_as_uint(o.w));
        }
    }
}

// ---------------- head MLP: one block per graph ----------------
__global__ __launch_bounds__(192) void k_final(const float* __restrict__ bl1,
                                               const float* __restrict__ bl2,
                                               float* __restrict__ out) {
    __shared__ float sh[3 * HID];
    __shared__ float sz1[2 * HID];
    __shared__ float sz2[HID / 2];
    int g = blockIdx.x;
    int tid = threadIdx.x;
    sh[tid] = __uint_as_float(g_hbits[g * (3 * HID) + tid]);
    __syncthreads();
    if (tid < 2 * HID) {
        float acc = bl1[tid];
#pragma unroll 4
        for (int c = 0; c < 3 * HID; c++) acc += sh[c] * g_Wl1T[c * (2 * HID) + tid];
        sz1[tid] = fmaxf(acc, 0.f);
    }
    __syncthreads();
    if (tid < HID / 2) {
        float acc = bl2[tid];
#pragma unroll 4
        for (int c = 0; c < 2 * HID; c++) acc += sz1[c] * g_Wl2T[c * (HID / 2) + tid];
        sz2[tid] = acc;
    }
    __syncthreads();
    if (tid < 32) {
        float v = sz2[tid];
        float q = v * v;
#pragma unroll
        for (int o = 16; o; o >>= 1) q += __shfl_xor_sync(0xFFFFFFFFu, q, o);
        float nrm = fmaxf(sqrtf(q), 1e-12f);
        out[g * 32 + tid] = v / nrm;
    }
}

// ---------------- launch ----------------
extern "C" void kernel_launch(void* const* d_in, const int* in_sizes, int n_in,
                              void* d_out, int out_size) {
    const float* x = (const float*)d_in[0];
    const int* ei = (const int*)d_in[1];
    const int* src = ei;
    const int* dst = ei + N_EDGES;
    const int* batch = (const int*)d_in[2];
    const float* t = (const float*)d_in[3];
    const float* W1r = (const float*)d_in[4];
    const float* b1 = (const float*)d_in[5];
    const float* W1s = (const float*)d_in[6];
    const float* W2r = (const float*)d_in[7];
    const float* b2 = (const float*)d_in[8];
    const float* W2s = (const float*)d_in[9];
    const float* W3r = (const float*)d_in[10];
    const float* b3 = (const float*)d_in[11];
    const float* W3s = (const float*)d_in[12];
    const float* Wl1 = (const float*)d_in[13];
    const float* bl1 = (const float*)d_in[14];
    const float* Wl2 = (const float*)d_in[15];
    const float* bl2 = (const float*)d_in[16];
    float* out = (float*)d_out;

    float *xpad, *bufA, *bufB, *aggr;
    cudaGetSymbolAddress((void**)&xpad, g_xpad);
    cudaGetSymbolAddress((void**)&bufA, g_bufA);
    cudaGetSymbolAddress((void**)&bufB, g_bufB);
    cudaGetSymbolAddress((void**)&aggr, g_aggr);

    const int PB = (N_NODES * C_PAD + 255) / 256;  // 6250
    const int EB = (N_EDGES + 255) / 256;          // 3125
    const int WB = (N_NODES * 32 + 255) / 256;     // warp-per-node: 6250
    const int LB = (N_NODES + 127) / 128;          // 391

    k_prep<<<PB, 256>>>(x, Wl1, Wl2);
    k_hist<<<EB, 256>>>(dst);
    k_scanA<<<SCAN_NB, SCAN_B>>>();
    k_scanB<<<1, 64>>>();
    k_scanC<<<SCAN_NB, SCAN_B>>>();
    k_scatter<<<EB, 256>>>(src, dst);

    // layer 1 (padded to 32 ch; channel 31 is exactly zero everywhere)
    k_aggr32<<<WB, 256>>>(xpad, t, aggr);
    k_lin<C_PAD, IN_CH><<<LB, 256>>>(xpad, aggr, W1r, b1, W1s, batch, 0, bufA);

    // layer 2
    k_aggr64<<<WB, 256>>>(bufA, t, aggr);
    k_lin<HID, HID><<<LB, 256>>>(bufA, aggr, W2r, b2, W2s, batch, HID, bufB);

    // layer 3
    k_aggr64<<<WB, 256>>>(bufB, t, aggr);
    k_lin<HID, HID><<<LB, 256>>>(bufB, aggr, W3r, b3, W3s, batch, 2 * HID, bufA);

    k_final<<<N_GRAPHS, 192>>>(bl1, bl2, out);
    (void)in_sizes; (void)n_in; (void)out_size;
}